// round 12
// baseline (speedup 1.0000x reference)
#include <cuda_runtime.h>

#define IN_DIM   128
#define OUT_DIM  128
#define N_NEIGH  32
#define BATCH    8192
#define WPB      8
#define THREADS  (WPB * 32)
#define GRID     (BATCH / WPB)

__device__ float g_v1[IN_DIM];
__device__ float g_v2[IN_DIM];
__device__ float g_c;
__device__ int   g_flag;   // 0 until block 0 publishes v1/v2/c
__device__ int   g_done;   // completion counter for replay-safe reset

// 8-array halving transpose-reduce over one 8-neighbor chunk.
// On entry p[k] = lane-partial of neighbor (8c+k). On exit, lane l with
// (l>>3)==c has m := full dot of neighbor 8c+(l&7).
__device__ __forceinline__ void reduce_chunk(float p[8], int lane, int c, float& m) {
    #pragma unroll
    for (int j = 0; j < 4; j++) {
        const bool hi = (lane & 16) != 0;
        float keep = hi ? p[j + 4] : p[j];
        float send = hi ? p[j]     : p[j + 4];
        p[j] = keep + __shfl_xor_sync(0xffffffffu, send, 16);
    }
    #pragma unroll
    for (int j = 0; j < 2; j++) {
        const bool hi = (lane & 8) != 0;
        float keep = hi ? p[j + 2] : p[j];
        float send = hi ? p[j]     : p[j + 2];
        p[j] = keep + __shfl_xor_sync(0xffffffffu, send, 8);
    }
    {
        const bool hi = (lane & 4) != 0;
        float keep = hi ? p[1] : p[0];
        float send = hi ? p[0] : p[1];
        p[0] = keep + __shfl_xor_sync(0xffffffffu, send, 4);
    }
    p[0] += __shfl_xor_sync(0xffffffffu, p[0], 2);
    p[0] += __shfl_xor_sync(0xffffffffu, p[0], 1);
    const float val = __shfl_sync(0xffffffffu, p[0], (lane & 7) << 2);
    if ((lane >> 3) == c) m = val;
}

__global__ __launch_bounds__(THREADS, 4)
void gat_fused_kernel(const float* __restrict__ ai_sq,
                      const float* __restrict__ ai_sn,
                      const float* __restrict__ W_w,
                      const float* __restrict__ W_b,
                      const float* __restrict__ u,
                      float* __restrict__ out)
{
    const int tid  = threadIdx.x;
    const int lane = tid & 31;
    const int warp = tid >> 5;

    __shared__ float  sv1[IN_DIM];
    __shared__ float  sv2[IN_DIM];
    __shared__ float  sc;
    __shared__ float  sbeta[N_NEIGH][WPB + 1];
    __shared__ float  su[2 * OUT_DIM];
    __shared__ float4 sp1[8][32];
    __shared__ float4 sp2[8][32];

    const int b0 = blockIdx.x * WPB;
    const int b  = b0 + warp;

    const size_t NSTR = (size_t)BATCH * (IN_DIM / 4);
    const float4* sn = reinterpret_cast<const float4*>(ai_sn)
                       + (size_t)b * (IN_DIM / 4) + lane;
    const float4* sq = reinterpret_cast<const float4*>(ai_sq) + (size_t)b * (IN_DIM / 4);

    float4 xp[8];
    float4 a;

    if (blockIdx.x == 0) {
        // ---- prep: v1 = W^T u1, v2 = W^T u2, c = b.(u1+u2) ----
        su[tid] = u[tid];                       // 256 floats = blockDim
        __syncthreads();

        const int i4 = tid & 31;                // float4 column over IN_DIM
        const int oc = tid >> 5;                // 0..7: 16 o's each
        float4 s1 = make_float4(0.f, 0.f, 0.f, 0.f);
        float4 s2 = make_float4(0.f, 0.f, 0.f, 0.f);
        const float4* W4 = reinterpret_cast<const float4*>(W_w);
        #pragma unroll 8
        for (int k = 0; k < 16; k++) {
            const int o = oc * 16 + k;
            float4 w = W4[o * 32 + i4];         // 16 independent LDG.128
            const float u1 = su[o], u2 = su[OUT_DIM + o];
            s1.x += w.x * u1; s1.y += w.y * u1; s1.z += w.z * u1; s1.w += w.w * u1;
            s2.x += w.x * u2; s2.y += w.y * u2; s2.z += w.z * u2; s2.w += w.w * u2;
        }
        sp1[oc][i4] = s1;
        sp2[oc][i4] = s2;
        __syncthreads();

        if (tid < 32) {
            float4 a1 = make_float4(0.f, 0.f, 0.f, 0.f);
            float4 a2 = make_float4(0.f, 0.f, 0.f, 0.f);
            #pragma unroll
            for (int k = 0; k < 8; k++) {
                float4 t1 = sp1[k][tid], t2 = sp2[k][tid];
                a1.x += t1.x; a1.y += t1.y; a1.z += t1.z; a1.w += t1.w;
                a2.x += t2.x; a2.y += t2.y; a2.z += t2.z; a2.w += t2.w;
            }
            reinterpret_cast<float4*>(g_v1)[tid] = a1;
            reinterpret_cast<float4*>(g_v2)[tid] = a2;
            __threadfence();
        } else if (tid < 64) {                  // warp 1: bias term
            const int l = tid - 32;
            float c = 0.f;
            #pragma unroll
            for (int k = 0; k < 4; k++) {
                const int o = l * 4 + k;
                c += W_b[o] * (su[o] + su[OUT_DIM + o]);
            }
            #pragma unroll
            for (int off = 16; off; off >>= 1)
                c += __shfl_xor_sync(0xffffffffu, c, off);
            if (l == 0) { g_c = c; __threadfence(); }
        }
        __syncthreads();
        if (tid == 0) *((volatile int*)&g_flag) = 1;   // publish

        // block 0 prefetches after prep (1/1024 of work: negligible delay)
        #pragma unroll
        for (int k = 0; k < 8; k++) xp[k] = __ldcs(&sn[(size_t)k * NSTR]);
        a = __ldcs(&sq[lane]);
    } else {
        // ---- prefetch chunk 0 + base row, THEN wait: prep hides under loads ----
        #pragma unroll
        for (int k = 0; k < 8; k++) xp[k] = __ldcs(&sn[(size_t)k * NSTR]);
        a = __ldcs(&sq[lane]);

        if (tid == 0) {
            while (*((volatile int*)&g_flag) == 0) __nanosleep(64);
            __threadfence();
        }
        __syncthreads();
    }

    // folded vectors -> smem -> registers
    if (tid < IN_DIM) { sv1[tid] = g_v1[tid]; sv2[tid] = g_v2[tid]; }
    if (tid == 0)     sc = g_c;
    __syncthreads();

    const float4 v1r = *reinterpret_cast<const float4*>(&sv1[lane * 4]);
    const float4 v2r = *reinterpret_cast<const float4*>(&sv2[lane * 4]);

    // base term from prefetched a
    float p0 = a.x * v1r.x + a.y * v1r.y + a.z * v1r.z + a.w * v1r.w;
    #pragma unroll
    for (int o = 16; o; o >>= 1) p0 += __shfl_xor_sync(0xffffffffu, p0, o);
    const float base = p0 + sc;

    float m = 0.f;      // lane l will hold mult[l, b]

    // chunk 0 from prefetched registers
    {
        float p[8];
        #pragma unroll
        for (int k = 0; k < 8; k++)
            p[k] = xp[k].x * v2r.x + xp[k].y * v2r.y + xp[k].z * v2r.z + xp[k].w * v2r.w;
        reduce_chunk(p, lane, 0, m);
    }

    // chunks 1..3
    #pragma unroll 1
    for (int c = 1; c < 4; c++) {
        float4 x[8];
        #pragma unroll
        for (int k = 0; k < 8; k++)
            x[k] = __ldcs(&sn[(size_t)(c * 8 + k) * NSTR]);
        float p[8];
        #pragma unroll
        for (int k = 0; k < 8; k++)
            p[k] = x[k].x * v2r.x + x[k].y * v2r.y + x[k].z * v2r.z + x[k].w * v2r.w;
        reduce_chunk(p, lane, c, m);
    }
    m += base;

    // leaky_relu(0.01) -> exp -> 32-way softmax across lanes
    const float lr   = (m >= 0.f) ? m : 0.01f * m;
    const float beta = expf(lr);
    float s = beta;
    #pragma unroll
    for (int o = 16; o; o >>= 1) s += __shfl_xor_sync(0xffffffffu, s, o);

    sbeta[lane][warp] = beta / s;
    __syncthreads();

    // coalesced store: out[n, b0:b0+8] in contiguous 32B segments
    const int n = tid >> 3;
    const int j = tid & 7;
    out[(size_t)n * BATCH + b0 + j] = sbeta[n][j];

    // replay-safe reset: last block restores g_flag/g_done to 0
    __syncthreads();
    if (tid == 0) {
        const int d = atomicAdd(&g_done, 1);
        if (d == GRID - 1) {
            g_done = 0;
            __threadfence();
            *((volatile int*)&g_flag) = 0;
        }
    }
}

extern "C" void kernel_launch(void* const* d_in, const int* in_sizes, int n_in,
                              void* d_out, int out_size) {
    const float* ai_sq = (const float*)d_in[0];
    const float* ai_sn = (const float*)d_in[1];
    const float* W_w   = (const float*)d_in[2];
    const float* W_b   = (const float*)d_in[3];
    const float* u     = (const float*)d_in[4];
    float* out = (float*)d_out;

    gat_fused_kernel<<<GRID, THREADS>>>(ai_sq, ai_sn, W_w, W_b, u, out);
}

// round 14
// speedup vs baseline: 1.0099x; 1.0099x over previous
#include <cuda_runtime.h>

#define IN_DIM   128
#define OUT_DIM  128
#define N_NEIGH  32
#define BATCH    8192
#define WPB      8
#define THREADS  (WPB * 32)
#define GRID     (BATCH / WPB)

__device__ float g_v1[IN_DIM];
__device__ float g_v2[IN_DIM];
__device__ float g_c;

// ---- prep: v1 = W^T u1, v2 = W^T u2, c = b.(u1+u2). 32 warps, float4 W loads ----
__global__ __launch_bounds__(1024)
void prep_kernel(const float* __restrict__ W_w,
                 const float* __restrict__ W_b,
                 const float* __restrict__ u) {
    const int t  = threadIdx.x;
    const int i4 = t & 31;             // float4 column over IN_DIM
    const int oc = t >> 5;             // 0..31: 4 o's each

    __shared__ float4 p1[32][32];      // [oc][i4] partials (16 KB x2)
    __shared__ float4 p2[32][32];

    const float4* W4 = reinterpret_cast<const float4*>(W_w);
    float4 s1 = make_float4(0.f, 0.f, 0.f, 0.f);
    float4 s2 = make_float4(0.f, 0.f, 0.f, 0.f);
    #pragma unroll
    for (int k = 0; k < 4; k++) {
        const int o = oc * 4 + k;
        float4 w = W4[o * 32 + i4];    // 4 independent LDG.128 per thread
        const float u1 = u[o], u2 = u[OUT_DIM + o];
        s1.x += w.x * u1; s1.y += w.y * u1; s1.z += w.z * u1; s1.w += w.w * u1;
        s2.x += w.x * u2; s2.y += w.y * u2; s2.z += w.z * u2; s2.w += w.w * u2;
    }
    p1[oc][i4] = s1;
    p2[oc][i4] = s2;
    __syncthreads();

    if (t < 32) {
        float4 a1 = make_float4(0.f, 0.f, 0.f, 0.f);
        float4 a2 = make_float4(0.f, 0.f, 0.f, 0.f);
        #pragma unroll
        for (int k = 0; k < 32; k++) {
            float4 t1 = p1[k][t], t2 = p2[k][t];
            a1.x += t1.x; a1.y += t1.y; a1.z += t1.z; a1.w += t1.w;
            a2.x += t2.x; a2.y += t2.y; a2.z += t2.z; a2.w += t2.w;
        }
        reinterpret_cast<float4*>(g_v1)[t] = a1;
        reinterpret_cast<float4*>(g_v2)[t] = a2;
    } else if (t < 64) {               // warp 1: bias term
        const int l = t - 32;
        float c = 0.f;
        #pragma unroll
        for (int k = 0; k < 4; k++) {
            const int o = l * 4 + k;
            c += W_b[o] * (u[o] + u[OUT_DIM + o]);
        }
        #pragma unroll
        for (int off = 16; off; off >>= 1)
            c += __shfl_xor_sync(0xffffffffu, c, off);
        if (l == 0) g_c = c;
    }
}

// 8-array halving transpose-reduce over one 8-neighbor chunk.
__device__ __forceinline__ void reduce_chunk(float p[8], int lane, int c, float& m) {
    #pragma unroll
    for (int j = 0; j < 4; j++) {
        const bool hi = (lane & 16) != 0;
        float keep = hi ? p[j + 4] : p[j];
        float send = hi ? p[j]     : p[j + 4];
        p[j] = keep + __shfl_xor_sync(0xffffffffu, send, 16);
    }
    #pragma unroll
    for (int j = 0; j < 2; j++) {
        const bool hi = (lane & 8) != 0;
        float keep = hi ? p[j + 2] : p[j];
        float send = hi ? p[j]     : p[j + 2];
        p[j] = keep + __shfl_xor_sync(0xffffffffu, send, 8);
    }
    {
        const bool hi = (lane & 4) != 0;
        float keep = hi ? p[1] : p[0];
        float send = hi ? p[0] : p[1];
        p[0] = keep + __shfl_xor_sync(0xffffffffu, send, 4);
    }
    p[0] += __shfl_xor_sync(0xffffffffu, p[0], 2);
    p[0] += __shfl_xor_sync(0xffffffffu, p[0], 1);
    const float val = __shfl_sync(0xffffffffu, p[0], (lane & 7) << 2);
    if ((lane >> 3) == c) m = val;
}

// ---- main: R11 body + PDL. Prefetch chunk 0, then wait for prep grid. ----
__global__ __launch_bounds__(THREADS, 5)
void gat_attn_kernel(const float* __restrict__ ai_sq,
                     const float* __restrict__ ai_sn,
                     float* __restrict__ out)
{
    const int tid  = threadIdx.x;
    const int lane = tid & 31;
    const int warp = tid >> 5;

    __shared__ float sv1[IN_DIM];
    __shared__ float sv2[IN_DIM];
    __shared__ float sc;
    __shared__ float sbeta[N_NEIGH][WPB + 1];

    const int b0 = blockIdx.x * WPB;
    const int b  = b0 + warp;

    const size_t NSTR = (size_t)BATCH * (IN_DIM / 4);
    const float4* sn = reinterpret_cast<const float4*>(ai_sn)
                       + (size_t)b * (IN_DIM / 4) + lane;
    const float4* sq = reinterpret_cast<const float4*>(ai_sq) + (size_t)b * (IN_DIM / 4);

    // prefetch: base row + chunk-0 loads go out while prep_kernel still runs
    float4 a = __ldcs(&sq[lane]);
    float4 xp[8];
    #pragma unroll
    for (int k = 0; k < 8; k++) xp[k] = __ldcs(&sn[(size_t)k * NSTR]);

    // PDL: block until prep grid's writes to g_v1/g_v2/g_c are visible
    cudaGridDependencySynchronize();

    if (tid < IN_DIM) { sv1[tid] = g_v1[tid]; sv2[tid] = g_v2[tid]; }
    if (tid == 0)     sc = g_c;
    __syncthreads();

    const float4 v1r = *reinterpret_cast<const float4*>(&sv1[lane * 4]);
    const float4 v2r = *reinterpret_cast<const float4*>(&sv2[lane * 4]);

    // base term
    float p0 = a.x * v1r.x + a.y * v1r.y + a.z * v1r.z + a.w * v1r.w;
    #pragma unroll
    for (int o = 16; o; o >>= 1) p0 += __shfl_xor_sync(0xffffffffu, p0, o);
    const float base = p0 + sc;

    float m = 0.f;                      // lane l will hold mult[l, b]

    // chunk 0 from prefetched registers
    {
        float p[8];
        #pragma unroll
        for (int k = 0; k < 8; k++)
            p[k] = xp[k].x * v2r.x + xp[k].y * v2r.y + xp[k].z * v2r.z + xp[k].w * v2r.w;
        reduce_chunk(p, lane, 0, m);
    }

    // chunks 1..3: batched 8-wide loads (MLP 8)
    #pragma unroll 1
    for (int c = 1; c < 4; c++) {
        float4 x[8];
        #pragma unroll
        for (int k = 0; k < 8; k++)
            x[k] = __ldcs(&sn[(size_t)(c * 8 + k) * NSTR]);
        float p[8];
        #pragma unroll
        for (int k = 0; k < 8; k++)
            p[k] = x[k].x * v2r.x + x[k].y * v2r.y + x[k].z * v2r.z + x[k].w * v2r.w;
        reduce_chunk(p, lane, c, m);
    }
    m += base;

    // leaky_relu(0.01) -> exp -> 32-way softmax across lanes
    const float lr   = (m >= 0.f) ? m : 0.01f * m;
    const float beta = expf(lr);
    float s = beta;
    #pragma unroll
    for (int o = 16; o; o >>= 1) s += __shfl_xor_sync(0xffffffffu, s, o);

    sbeta[lane][warp] = beta / s;
    __syncthreads();

    // coalesced store: out[n, b0:b0+8] in contiguous 32B segments
    const int n = tid >> 3;
    const int j = tid & 7;
    out[(size_t)n * BATCH + b0 + j] = sbeta[n][j];
}

extern "C" void kernel_launch(void* const* d_in, const int* in_sizes, int n_in,
                              void* d_out, int out_size) {
    const float* ai_sq = (const float*)d_in[0];
    const float* ai_sn = (const float*)d_in[1];
    const float* W_w   = (const float*)d_in[2];
    const float* W_b   = (const float*)d_in[3];
    const float* u     = (const float*)d_in[4];
    float* out = (float*)d_out;

    prep_kernel<<<1, 1024>>>(W_w, W_b, u);

    // main kernel with programmatic dependent launch: overlaps with prep
    cudaLaunchConfig_t cfg = {};
    cfg.gridDim  = dim3(GRID);
    cfg.blockDim = dim3(THREADS);
    cfg.dynamicSmemBytes = 0;
    cfg.stream = 0;                    // same (legacy default) stream as prep
    cudaLaunchAttribute attr[1];
    attr[0].id = cudaLaunchAttributeProgrammaticStreamSerialization;
    attr[0].val.programmaticStreamSerializationAllowed = 1;
    cfg.attrs = attr;
    cfg.numAttrs = 1;
    cudaLaunchKernelEx(&cfg, gat_attn_kernel, ai_sq, ai_sn, out);
}

// round 15
// speedup vs baseline: 1.0245x; 1.0145x over previous
#include <cuda_runtime.h>

#define IN_DIM   128
#define OUT_DIM  128
#define N_NEIGH  32
#define BATCH    8192
#define WPB      8
#define THREADS  (WPB * 32)
#define GRID     (BATCH / WPB)

__device__ float g_v1[IN_DIM];
__device__ float g_v2[IN_DIM];
__device__ float g_c;

// ---- prep: v1 = W^T u1, v2 = W^T u2, c = b.(u1+u2). 32 warps, float4 W loads ----
__global__ __launch_bounds__(1024)
void prep_kernel(const float* __restrict__ W_w,
                 const float* __restrict__ W_b,
                 const float* __restrict__ u) {
    // EARLY TRIGGER: let the dependent main grid launch NOW, so its prefetch
    // overlaps this kernel. cudaGridDependencySynchronize() in the main kernel
    // still waits for this grid's completion + memory flush.
    cudaTriggerProgrammaticLaunchCompletion();

    const int t  = threadIdx.x;
    const int i4 = t & 31;             // float4 column over IN_DIM
    const int oc = t >> 5;             // 0..31: 4 o's each

    __shared__ float4 p1[32][32];
    __shared__ float4 p2[32][32];

    const float4* W4 = reinterpret_cast<const float4*>(W_w);
    float4 s1 = make_float4(0.f, 0.f, 0.f, 0.f);
    float4 s2 = make_float4(0.f, 0.f, 0.f, 0.f);
    #pragma unroll
    for (int k = 0; k < 4; k++) {
        const int o = oc * 4 + k;
        float4 w = W4[o * 32 + i4];    // 4 independent LDG.128 per thread
        const float u1 = u[o], u2 = u[OUT_DIM + o];
        s1.x += w.x * u1; s1.y += w.y * u1; s1.z += w.z * u1; s1.w += w.w * u1;
        s2.x += w.x * u2; s2.y += w.y * u2; s2.z += w.z * u2; s2.w += w.w * u2;
    }
    p1[oc][i4] = s1;
    p2[oc][i4] = s2;
    __syncthreads();

    if (t < 32) {
        float4 a1 = make_float4(0.f, 0.f, 0.f, 0.f);
        float4 a2 = make_float4(0.f, 0.f, 0.f, 0.f);
        #pragma unroll
        for (int k = 0; k < 32; k++) {
            float4 t1 = p1[k][t], t2 = p2[k][t];
            a1.x += t1.x; a1.y += t1.y; a1.z += t1.z; a1.w += t1.w;
            a2.x += t2.x; a2.y += t2.y; a2.z += t2.z; a2.w += t2.w;
        }
        reinterpret_cast<float4*>(g_v1)[t] = a1;
        reinterpret_cast<float4*>(g_v2)[t] = a2;
    } else if (t < 64) {               // warp 1: bias term
        const int l = t - 32;
        float c = 0.f;
        #pragma unroll
        for (int k = 0; k < 4; k++) {
            const int o = l * 4 + k;
            c += W_b[o] * (u[o] + u[OUT_DIM + o]);
        }
        #pragma unroll
        for (int off = 16; off; off >>= 1)
            c += __shfl_xor_sync(0xffffffffu, c, off);
        if (l == 0) g_c = c;
    }
}

// 8-array halving transpose-reduce over one 8-neighbor chunk.
__device__ __forceinline__ void reduce_chunk(float p[8], int lane, int c, float& m) {
    #pragma unroll
    for (int j = 0; j < 4; j++) {
        const bool hi = (lane & 16) != 0;
        float keep = hi ? p[j + 4] : p[j];
        float send = hi ? p[j]     : p[j + 4];
        p[j] = keep + __shfl_xor_sync(0xffffffffu, send, 16);
    }
    #pragma unroll
    for (int j = 0; j < 2; j++) {
        const bool hi = (lane & 8) != 0;
        float keep = hi ? p[j + 2] : p[j];
        float send = hi ? p[j]     : p[j + 2];
        p[j] = keep + __shfl_xor_sync(0xffffffffu, send, 8);
    }
    {
        const bool hi = (lane & 4) != 0;
        float keep = hi ? p[1] : p[0];
        float send = hi ? p[0] : p[1];
        p[0] = keep + __shfl_xor_sync(0xffffffffu, send, 4);
    }
    p[0] += __shfl_xor_sync(0xffffffffu, p[0], 2);
    p[0] += __shfl_xor_sync(0xffffffffu, p[0], 1);
    const float val = __shfl_sync(0xffffffffu, p[0], (lane & 7) << 2);
    if ((lane >> 3) == c) m = val;
}

// ---- main: prefetch chunk 0 under prep (true PDL overlap), then stream ----
__global__ __launch_bounds__(THREADS, 5)
void gat_attn_kernel(const float* __restrict__ ai_sq,
                     const float* __restrict__ ai_sn,
                     float* __restrict__ out)
{
    const int tid  = threadIdx.x;
    const int lane = tid & 31;
    const int warp = tid >> 5;

    __shared__ float sv1[IN_DIM];
    __shared__ float sv2[IN_DIM];
    __shared__ float sc;
    __shared__ float sbeta[N_NEIGH][WPB + 1];

    const int b0 = blockIdx.x * WPB;
    const int b  = b0 + warp;

    const size_t NSTR = (size_t)BATCH * (IN_DIM / 4);
    const float4* sn = reinterpret_cast<const float4*>(ai_sn)
                       + (size_t)b * (IN_DIM / 4) + lane;
    const float4* sq = reinterpret_cast<const float4*>(ai_sq) + (size_t)b * (IN_DIM / 4);

    // prefetch while prep_kernel runs (launched via early trigger)
    float4 a = __ldcs(&sq[lane]);
    float4 xp[8];
    #pragma unroll
    for (int k = 0; k < 8; k++) xp[k] = __ldcs(&sn[(size_t)k * NSTR]);

    // wait for prep grid's writes to g_v1/g_v2/g_c
    cudaGridDependencySynchronize();

    if (tid < IN_DIM) { sv1[tid] = g_v1[tid]; sv2[tid] = g_v2[tid]; }
    if (tid == 0)     sc = g_c;
    __syncthreads();

    const float4 v1r = *reinterpret_cast<const float4*>(&sv1[lane * 4]);
    const float4 v2r = *reinterpret_cast<const float4*>(&sv2[lane * 4]);

    // base term
    float p0 = a.x * v1r.x + a.y * v1r.y + a.z * v1r.z + a.w * v1r.w;
    #pragma unroll
    for (int o = 16; o; o >>= 1) p0 += __shfl_xor_sync(0xffffffffu, p0, o);
    const float base = p0 + sc;

    float m = 0.f;                      // lane l will hold mult[l, b]

    // chunk 0 from prefetched registers
    {
        float p[8];
        #pragma unroll
        for (int k = 0; k < 8; k++)
            p[k] = xp[k].x * v2r.x + xp[k].y * v2r.y + xp[k].z * v2r.z + xp[k].w * v2r.w;
        reduce_chunk(p, lane, 0, m);
    }

    // chunks 1..3: batched 8-wide loads (MLP 8)
    #pragma unroll 1
    for (int c = 1; c < 4; c++) {
        float4 x[8];
        #pragma unroll
        for (int k = 0; k < 8; k++)
            x[k] = __ldcs(&sn[(size_t)(c * 8 + k) * NSTR]);
        float p[8];
        #pragma unroll
        for (int k = 0; k < 8; k++)
            p[k] = x[k].x * v2r.x + x[k].y * v2r.y + x[k].z * v2r.z + x[k].w * v2r.w;
        reduce_chunk(p, lane, c, m);
    }
    m += base;

    // leaky_relu(0.01) -> exp -> 32-way softmax across lanes
    const float lr   = (m >= 0.f) ? m : 0.01f * m;
    const float beta = expf(lr);
    float s = beta;
    #pragma unroll
    for (int o = 16; o; o >>= 1) s += __shfl_xor_sync(0xffffffffu, s, o);

    sbeta[lane][warp] = beta / s;
    __syncthreads();

    // coalesced store: out[n, b0:b0+8] in contiguous 32B segments
    const int n = tid >> 3;
    const int j = tid & 7;
    out[(size_t)n * BATCH + b0 + j] = sbeta[n][j];
}

extern "C" void kernel_launch(void* const* d_in, const int* in_sizes, int n_in,
                              void* d_out, int out_size) {
    const float* ai_sq = (const float*)d_in[0];
    const float* ai_sn = (const float*)d_in[1];
    const float* W_w   = (const float*)d_in[2];
    const float* W_b   = (const float*)d_in[3];
    const float* u     = (const float*)d_in[4];
    float* out = (float*)d_out;

    prep_kernel<<<1, 1024>>>(W_w, W_b, u);

    // dependent launch: main grid may start as soon as prep triggers (first instr)
    cudaLaunchConfig_t cfg = {};
    cfg.gridDim  = dim3(GRID);
    cfg.blockDim = dim3(THREADS);
    cfg.dynamicSmemBytes = 0;
    cfg.stream = 0;
    cudaLaunchAttribute attr[1];
    attr[0].id = cudaLaunchAttributeProgrammaticStreamSerialization;
    attr[0].val.programmaticStreamSerializationAllowed = 1;
    cfg.attrs = attr;
    cfg.numAttrs = 1;
    cudaLaunchKernelEx(&cfg, gat_attn_kernel, ai_sq, ai_sn, out);
}

// round 17
// speedup vs baseline: 1.0723x; 1.0466x over previous
#include <cuda_runtime.h>

#define IN_DIM   128
#define OUT_DIM  128
#define N_NEIGH  32
#define BATCH    8192
#define WPB      8
#define THREADS  (WPB * 32)
#define GRID     (BATCH / WPB)

__device__ float g_v1[IN_DIM];
__device__ float g_v2[IN_DIM];
__device__ float g_c;

// ---- prep: v1 = W^T u1, v2 = W^T u2, c = b.(u1+u2). Fast 2-stage reduce. ----
__global__ __launch_bounds__(1024)
void prep_kernel(const float* __restrict__ W_w,
                 const float* __restrict__ W_b,
                 const float* __restrict__ u) {
    // EARLY TRIGGER: dependent main grid launches immediately; its prefetch
    // overlaps this kernel. GridDependencySynchronize still fences our writes.
    cudaTriggerProgrammaticLaunchCompletion();

    const int t  = threadIdx.x;
    const int i4 = t & 31;             // float4 column over IN_DIM
    const int oc = t >> 5;             // 0..31: 4 o's each

    __shared__ float4 p1[32][32];      // [oc][i4]
    __shared__ float4 p2[32][32];
    __shared__ float4 q1[8][32];       // [g][i4] stage-A results
    __shared__ float4 q2[8][32];

    const float4* W4 = reinterpret_cast<const float4*>(W_w);
    float4 s1 = make_float4(0.f, 0.f, 0.f, 0.f);
    float4 s2 = make_float4(0.f, 0.f, 0.f, 0.f);
    #pragma unroll
    for (int k = 0; k < 4; k++) {
        const int o = oc * 4 + k;
        float4 w = W4[o * 32 + i4];    // 4 independent LDG.128 per thread
        const float u1 = u[o], u2 = u[OUT_DIM + o];
        s1.x += w.x * u1; s1.y += w.y * u1; s1.z += w.z * u1; s1.w += w.w * u1;
        s2.x += w.x * u2; s2.y += w.y * u2; s2.z += w.z * u2; s2.w += w.w * u2;
    }
    p1[oc][i4] = s1;
    p2[oc][i4] = s2;
    __syncthreads();

    // stage A: 256 threads, each sums 4 oc-partials for one (g, i4)
    if (t < 256) {
        const int g = t >> 5;          // 0..7
        float4 a1 = make_float4(0.f, 0.f, 0.f, 0.f);
        float4 a2 = make_float4(0.f, 0.f, 0.f, 0.f);
        #pragma unroll
        for (int k = 0; k < 4; k++) {
            const int o = g + 8 * k;
            float4 t1 = p1[o][i4], t2 = p2[o][i4];
            a1.x += t1.x; a1.y += t1.y; a1.z += t1.z; a1.w += t1.w;
            a2.x += t2.x; a2.y += t2.y; a2.z += t2.z; a2.w += t2.w;
        }
        q1[g][i4] = a1;
        q2[g][i4] = a2;
    } else if (t < 288) {              // warp 8: bias term in parallel
        const int l = t - 256;
        float c = 0.f;
        #pragma unroll
        for (int k = 0; k < 4; k++) {
            const int o = l * 4 + k;
            c += W_b[o] * (u[o] + u[OUT_DIM + o]);
        }
        #pragma unroll
        for (int off = 16; off; off >>= 1)
            c += __shfl_xor_sync(0xffffffffu, c, off);
        if (l == 0) g_c = c;
    }
    __syncthreads();

    // stage B: 32 threads, each sums the 8 group results
    if (t < 32) {
        float4 a1 = make_float4(0.f, 0.f, 0.f, 0.f);
        float4 a2 = make_float4(0.f, 0.f, 0.f, 0.f);
        #pragma unroll
        for (int k = 0; k < 8; k++) {
            float4 t1 = q1[k][t], t2 = q2[k][t];
            a1.x += t1.x; a1.y += t1.y; a1.z += t1.z; a1.w += t1.w;
            a2.x += t2.x; a2.y += t2.y; a2.z += t2.z; a2.w += t2.w;
        }
        reinterpret_cast<float4*>(g_v1)[t] = a1;
        reinterpret_cast<float4*>(g_v2)[t] = a2;
    }
}

// 8-array halving transpose-reduce over one 8-neighbor chunk.
__device__ __forceinline__ void reduce_chunk(float p[8], int lane, int c, float& m) {
    #pragma unroll
    for (int j = 0; j < 4; j++) {
        const bool hi = (lane & 16) != 0;
        float keep = hi ? p[j + 4] : p[j];
        float send = hi ? p[j]     : p[j + 4];
        p[j] = keep + __shfl_xor_sync(0xffffffffu, send, 16);
    }
    #pragma unroll
    for (int j = 0; j < 2; j++) {
        const bool hi = (lane & 8) != 0;
        float keep = hi ? p[j + 2] : p[j];
        float send = hi ? p[j]     : p[j + 2];
        p[j] = keep + __shfl_xor_sync(0xffffffffu, send, 8);
    }
    {
        const bool hi = (lane & 4) != 0;
        float keep = hi ? p[1] : p[0];
        float send = hi ? p[0] : p[1];
        p[0] = keep + __shfl_xor_sync(0xffffffffu, send, 4);
    }
    p[0] += __shfl_xor_sync(0xffffffffu, p[0], 2);
    p[0] += __shfl_xor_sync(0xffffffffu, p[0], 1);
    const float val = __shfl_sync(0xffffffffu, p[0], (lane & 7) << 2);
    if ((lane >> 3) == c) m = val;
}

// ---- main: prefetch under prep (PDL), rotated chunk order for desync ----
__global__ __launch_bounds__(THREADS, 5)
void gat_attn_kernel(const float* __restrict__ ai_sq,
                     const float* __restrict__ ai_sn,
                     float* __restrict__ out)
{
    const int tid  = threadIdx.x;
    const int lane = tid & 31;
    const int warp = tid >> 5;

    __shared__ float sv1[IN_DIM];
    __shared__ float sv2[IN_DIM];
    __shared__ float sc;
    __shared__ float sbeta[N_NEIGH][WPB + 1];

    const int b0 = blockIdx.x * WPB;
    const int b  = b0 + warp;
    const int c0 = blockIdx.x & 3;         // rotated chunk start per block

    const size_t NSTR = (size_t)BATCH * (IN_DIM / 4);
    const float4* sn = reinterpret_cast<const float4*>(ai_sn)
                       + (size_t)b * (IN_DIM / 4) + lane;
    const float4* sq = reinterpret_cast<const float4*>(ai_sq) + (size_t)b * (IN_DIM / 4);

    // prefetch chunk c0 + base row while prep_kernel runs
    float4 a = __ldcs(&sq[lane]);
    float4 xp[8];
    #pragma unroll
    for (int k = 0; k < 8; k++) xp[k] = __ldcs(&sn[(size_t)(c0 * 8 + k) * NSTR]);

    // wait for prep grid's g_v1/g_v2/g_c
    cudaGridDependencySynchronize();

    if (tid < IN_DIM) { sv1[tid] = g_v1[tid]; sv2[tid] = g_v2[tid]; }
    if (tid == 0)     sc = g_c;
    __syncthreads();

    const float4 v1r = *reinterpret_cast<const float4*>(&sv1[lane * 4]);
    const float4 v2r = *reinterpret_cast<const float4*>(&sv2[lane * 4]);

    // base term
    float p0 = a.x * v1r.x + a.y * v1r.y + a.z * v1r.z + a.w * v1r.w;
    #pragma unroll
    for (int o = 16; o; o >>= 1) p0 += __shfl_xor_sync(0xffffffffu, p0, o);
    const float base = p0 + sc;

    float m = 0.f;                         // lane l will hold mult[l, b]

    // chunk c0 from prefetched registers
    {
        float p[8];
        #pragma unroll
        for (int k = 0; k < 8; k++)
            p[k] = xp[k].x * v2r.x + xp[k].y * v2r.y + xp[k].z * v2r.z + xp[k].w * v2r.w;
        reduce_chunk(p, lane, c0, m);
    }

    // remaining 3 chunks, rotated order
    #pragma unroll 1
    for (int kk = 1; kk < 4; kk++) {
        const int c = (c0 + kk) & 3;
        float4 x[8];
        #pragma unroll
        for (int k = 0; k < 8; k++)
            x[k] = __ldcs(&sn[(size_t)(c * 8 + k) * NSTR]);
        float p[8];
        #pragma unroll
        for (int k = 0; k < 8; k++)
            p[k] = x[k].x * v2r.x + x[k].y * v2r.y + x[k].z * v2r.z + x[k].w * v2r.w;
        reduce_chunk(p, lane, c, m);
    }
    m += base;

    // leaky_relu(0.01) -> exp -> 32-way softmax across lanes
    const float lr   = (m >= 0.f) ? m : 0.01f * m;
    const float beta = expf(lr);
    float s = beta;
    #pragma unroll
    for (int o = 16; o; o >>= 1) s += __shfl_xor_sync(0xffffffffu, s, o);

    sbeta[lane][warp] = beta / s;
    __syncthreads();

    // coalesced store: out[n, b0:b0+8] in contiguous 32B segments
    const int n = tid >> 3;
    const int j = tid & 7;
    out[(size_t)n * BATCH + b0 + j] = sbeta[n][j];
}

extern "C" void kernel_launch(void* const* d_in, const int* in_sizes, int n_in,
                              void* d_out, int out_size) {
    const float* ai_sq = (const float*)d_in[0];
    const float* ai_sn = (const float*)d_in[1];
    const float* W_w   = (const float*)d_in[2];
    const float* W_b   = (const float*)d_in[3];
    const float* u     = (const float*)d_in[4];
    float* out = (float*)d_out;

    prep_kernel<<<1, 1024>>>(W_w, W_b, u);

    cudaLaunchConfig_t cfg = {};
    cfg.gridDim  = dim3(GRID);
    cfg.blockDim = dim3(THREADS);
    cfg.dynamicSmemBytes = 0;
    cfg.stream = 0;
    cudaLaunchAttribute attr[1];
    attr[0].id = cudaLaunchAttributeProgrammaticStreamSerialization;
    attr[0].val.programmaticStreamSerializationAllowed = 1;
    cfg.attrs = attr;
    cfg.numAttrs = 1;
    cudaLaunchKernelEx(&cfg, gat_attn_kernel, ai_sq, ai_sn, out);
}